// round 1
// baseline (speedup 1.0000x reference)
#include <cuda_runtime.h>

// Shapes (fixed by the problem): N=100000, D=64, H=128, E=1600000
#define Dk     64
#define Hk     128
#define TE     128      // edges per tile
#define PITCH  132      // smem row pitch (floats) to avoid stride-128 bank conflicts
#define MAXN   100000

// Scratch: U = nodes @ W1[0:64,:], V = nodes @ W1[64:128,:]   (each N x 128 fp32)
__device__ float g_U[(size_t)MAXN * Hk];
__device__ float g_V[(size_t)MAXN * Hk];

__device__ __forceinline__ void red_add_v4(float* addr, float x, float y, float z, float w) {
    asm volatile("red.global.add.v4.f32 [%0], {%1,%2,%3,%4};"
                 :: "l"(addr), "f"(x), "f"(y), "f"(z), "f"(w) : "memory");
}

// ---------------- Kernel 0: out = nodes ----------------
__global__ __launch_bounds__(256) void copy_kernel(const float* __restrict__ nodes,
                                                   float* __restrict__ out, int n4) {
    int i = blockIdx.x * blockDim.x + threadIdx.x;
    if (i < n4) ((float4*)out)[i] = ((const float4*)nodes)[i];
}

// ---------------- Kernel A: U/V precompute ----------------
// Per block: 128-node tile. smem: Ns[64][PITCH] (k-major) + W1s[128][128].
__global__ __launch_bounds__(256) void uv_kernel(const float* __restrict__ nodes,
                                                 const float* __restrict__ W1, int N) {
    extern __shared__ float smem[];
    float* Ns  = smem;               // [64][PITCH], Ns[k][n]
    float* W1s = smem + 64 * PITCH;  // [128][128]

    int tid = threadIdx.x;
    for (int idx = tid; idx < 128 * 128; idx += 256) W1s[idx] = W1[idx];

    int n_base = blockIdx.x * 128;
    for (int idx = tid; idx < 128 * 64; idx += 256) {
        int k = idx & 63, n = idx >> 6;
        int gn = n_base + n;
        Ns[k * PITCH + n] = (gn < N) ? nodes[gn * Dk + k] : 0.f;
    }
    __syncthreads();

    int ty = tid >> 4, tx = tid & 15;
    int n0 = ty * 8, c0 = tx * 8;

    #pragma unroll
    for (int pass = 0; pass < 2; pass++) {
        const float* Wb = W1s + pass * 64 * 128;
        float acc[8][8];
        #pragma unroll
        for (int a = 0; a < 8; a++)
            #pragma unroll
            for (int b = 0; b < 8; b++) acc[a][b] = 0.f;

        #pragma unroll 4
        for (int k = 0; k < 64; k++) {
            float4 a0 = *(const float4*)&Ns[k * PITCH + n0];
            float4 a1 = *(const float4*)&Ns[k * PITCH + n0 + 4];
            float4 w0 = *(const float4*)&Wb[k * 128 + c0];
            float4 w1 = *(const float4*)&Wb[k * 128 + c0 + 4];
            float af[8] = {a0.x, a0.y, a0.z, a0.w, a1.x, a1.y, a1.z, a1.w};
            float wf[8] = {w0.x, w0.y, w0.z, w0.w, w1.x, w1.y, w1.z, w1.w};
            #pragma unroll
            for (int a = 0; a < 8; a++)
                #pragma unroll
                for (int b = 0; b < 8; b++) acc[a][b] += af[a] * wf[b];
        }

        float* Out = pass ? g_V : g_U;
        #pragma unroll
        for (int a = 0; a < 8; a++) {
            int gn = n_base + n0 + a;
            if (gn < N) {
                *(float4*)&Out[(size_t)gn * Hk + c0] =
                    make_float4(acc[a][0], acc[a][1], acc[a][2], acc[a][3]);
                *(float4*)&Out[(size_t)gn * Hk + c0 + 4] =
                    make_float4(acc[a][4], acc[a][5], acc[a][6], acc[a][7]);
            }
        }
    }
}

// ---------------- Kernel B: per-edge layer-1 gather + layer-2 GEMM + scatter ----
// Tile of 128 edges per block.
// dir 0: H = relu(U[i] + V[j] + b1); M = H@W2 + b2; out[i] += M
// dir 1: H = relu(U[j] + V[i] + b1); M = H@W2 + b2; out[j] += M
// smem ~102KB -> 2 CTAs/SM for overlap.
__global__ __launch_bounds__(256, 2) void edge_kernel(const int* __restrict__ edges,
                                                      const float* __restrict__ W2,
                                                      const float* __restrict__ b1,
                                                      const float* __restrict__ b2,
                                                      float* __restrict__ out, int E) {
    extern __shared__ float smem[];
    float* Hs  = smem;                   // [TE][PITCH]  H[e][c]
    float* W2s = Hs + TE * PITCH;        // [128][64]
    float* b1s = W2s + Hk * Dk;          // 128
    float* b2s = b1s + Hk;               // 64
    int*   eis = (int*)(b2s + Dk);       // 128
    int*   ejs = eis + TE;               // 128

    int tid = threadIdx.x;
    for (int idx = tid; idx < Hk * Dk; idx += 256) W2s[idx] = W2[idx];
    if (tid < Hk) b1s[tid] = b1[tid];
    if (tid < Dk) b2s[tid] = b2[tid];

    int ebase = blockIdx.x * TE;
    if (tid < TE) {
        int e = ebase + tid;
        int a = 0, b = 0;
        if (e < E) { a = edges[2 * e]; b = edges[2 * e + 1]; }
        eis[tid] = a; ejs[tid] = b;
    }
    __syncthreads();

    int ty = tid >> 4, tx = tid & 15;
    int e0 = ty * 8, d0 = tx * 4;

    #pragma unroll
    for (int dir = 0; dir < 2; dir++) {
        const int* sn = dir ? ejs : eis;   // U-index and scatter target
        const int* on = dir ? eis : ejs;   // V-index

        // ---- layer-1: gather + bias + relu into Hs ----
        #pragma unroll
        for (int it = 0; it < 16; it++) {
            int idx = tid + it * 256;            // < TE*32
            int e = idx >> 5;
            int c = (idx & 31) << 2;
            int na = sn[e], nb = on[e];
            float4 u = *(const float4*)&g_U[(size_t)na * Hk + c];
            float4 v = *(const float4*)&g_V[(size_t)nb * Hk + c];
            float4 bb = *(const float4*)&b1s[c];
            float4 h;
            h.x = fmaxf(u.x + v.x + bb.x, 0.f);
            h.y = fmaxf(u.y + v.y + bb.y, 0.f);
            h.z = fmaxf(u.z + v.z + bb.z, 0.f);
            h.w = fmaxf(u.w + v.w + bb.w, 0.f);
            *(float4*)&Hs[e * PITCH + c] = h;
        }
        __syncthreads();

        // ---- layer-2: M[e][d] = sum_c Hs[e][c] * W2[c][d] + b2[d] ----
        float m[8][4];
        float4 bias = *(const float4*)&b2s[d0];
        #pragma unroll
        for (int a = 0; a < 8; a++) {
            m[a][0] = bias.x; m[a][1] = bias.y; m[a][2] = bias.z; m[a][3] = bias.w;
        }
        const float* hrow = &Hs[e0 * PITCH];
        #pragma unroll 4
        for (int c = 0; c < Hk; c++) {
            float4 w = *(const float4*)&W2s[c * Dk + d0];
            #pragma unroll
            for (int a = 0; a < 8; a++) {
                float hv = hrow[a * PITCH + c];
                m[a][0] += hv * w.x;
                m[a][1] += hv * w.y;
                m[a][2] += hv * w.z;
                m[a][3] += hv * w.w;
            }
        }

        // ---- scatter ----
        #pragma unroll
        for (int a = 0; a < 8; a++) {
            int e = ebase + e0 + a;
            if (e < E) {
                float* addr = out + (size_t)sn[e0 + a] * Dk + d0;
                red_add_v4(addr, m[a][0], m[a][1], m[a][2], m[a][3]);
            }
        }
        __syncthreads();  // protect Hs before next dir overwrites
    }
}

extern "C" void kernel_launch(void* const* d_in, const int* in_sizes, int n_in,
                              void* d_out, int out_size) {
    const float* nodes = (const float*)d_in[0];
    const int*   edges = (const int*)d_in[1];
    const float* W1    = (const float*)d_in[2];
    const float* b1    = (const float*)d_in[3];
    const float* W2    = (const float*)d_in[4];
    const float* b2    = (const float*)d_in[5];
    float* out = (float*)d_out;

    int N = in_sizes[0] / Dk;
    int E = in_sizes[1] / 2;

    static bool attr_set = false;
    const int uv_smem   = (64 * PITCH + 128 * 128) * 4;
    const int edge_smem = (TE * PITCH + Hk * Dk + Hk + Dk) * 4 + 2 * TE * 4;
    if (!attr_set) {
        cudaFuncSetAttribute(uv_kernel,   cudaFuncAttributeMaxDynamicSharedMemorySize, uv_smem);
        cudaFuncSetAttribute(edge_kernel, cudaFuncAttributeMaxDynamicSharedMemorySize, edge_smem);
        attr_set = true;
    }

    // out = nodes
    int n4 = (N * Dk) / 4;
    copy_kernel<<<(n4 + 255) / 256, 256>>>(nodes, out, n4);

    // U/V precompute
    int uv_blocks = (N + 127) / 128;
    uv_kernel<<<uv_blocks, 256, uv_smem>>>(nodes, W1, N);

    // edge messages + scatter
    int tiles = (E + TE - 1) / TE;
    edge_kernel<<<tiles, 256, edge_smem>>>(edges, W2, b1, b2, out, E);
}

// round 4
// speedup vs baseline: 1.6510x; 1.6510x over previous
#include <cuda_runtime.h>
#include <cstdint>

// Shapes: N=100000, D=64, H=128, E=1600000
#define Dk     64
#define Hk     128
#define TE     128      // edges per tile
#define UVP    132
#define HSP    136      // Hs pitch (floats)
#define W2P    136      // W2s pitch (floats)
#define MAXN   100000

// Scratch: U = nodes @ W1[:64,:] (columns permuted), V = nodes @ W1[64:,:]
__device__ float g_U[(size_t)MAXN * Hk];
__device__ float g_V[(size_t)MAXN * Hk];

// hidden-dim permutation within each 8-group: position s holds unit u[s]
__device__ __constant__ int c_perm[8] = {0, 4, 1, 5, 2, 6, 3, 7};

// ---------------- smem float-index layout for edge kernel ----------------
#define F_HS   0                         // [128][HSP]
#define F_W2   (F_HS + TE * HSP)         // [64][W2P]
#define F_B1   (F_W2 + Dk * W2P)         // 128 (permuted)
#define F_B2   (F_B1 + Hk)               // 64
#define F_EIS  (F_B2 + Dk)               // 128 ints
#define F_EJS  (F_EIS + TE)
#define F_TOT  (F_EJS + TE)
#define EDGE_SMEM_BYTES (F_TOT * 4)

extern __shared__ char smem_raw[];

__device__ __forceinline__ float to_tf32(float x) {
    float y; asm("cvt.rna.tf32.f32 %0, %1;" : "=f"(y) : "f"(x)); return y;
}
__device__ __forceinline__ void red_add_v2(float* addr, float x, float y) {
    asm volatile("red.global.add.v2.f32 [%0], {%1,%2};"
                 :: "l"(addr), "f"(x), "f"(y) : "memory");
}
__device__ __forceinline__ void mma_tf32(float c[4],
                                         uint32_t a0, uint32_t a1, uint32_t a2, uint32_t a3,
                                         uint32_t b0, uint32_t b1) {
    asm volatile(
        "mma.sync.aligned.m16n8k8.row.col.f32.tf32.tf32.f32 "
        "{%0,%1,%2,%3}, {%4,%5,%6,%7}, {%8,%9}, {%0,%1,%2,%3};"
        : "+f"(c[0]), "+f"(c[1]), "+f"(c[2]), "+f"(c[3])
        : "r"(a0), "r"(a1), "r"(a2), "r"(a3), "r"(b0), "r"(b1));
}

// ---------------- Kernel 0: out = nodes ----------------
__global__ __launch_bounds__(256) void copy_kernel(const float* __restrict__ nodes,
                                                   float* __restrict__ out, int n4) {
    int i = blockIdx.x * blockDim.x + threadIdx.x;
    if (i < n4) ((float4*)out)[i] = ((const float4*)nodes)[i];
}

// ---------------- Kernel A: U/V precompute (fp32 SIMT, permuted columns) ----
__global__ __launch_bounds__(256) void uv_kernel(const float* __restrict__ nodes,
                                                 const float* __restrict__ W1, int N) {
    float* smem = (float*)smem_raw;
    float* Ns  = smem;               // [64][UVP]
    float* W1s = smem + 64 * UVP;    // [128][128] (columns permuted)

    int tid = threadIdx.x;
    for (int idx = tid; idx < 128 * 128; idx += 256) {
        int c = idx & 127;
        int src_c = (c & ~7) + c_perm[c & 7];
        W1s[idx] = W1[(idx & ~127) + src_c];
    }

    int n_base = blockIdx.x * 128;
    for (int idx = tid; idx < 128 * 64; idx += 256) {
        int k = idx & 63, n = idx >> 6;
        int gn = n_base + n;
        Ns[k * UVP + n] = (gn < N) ? nodes[gn * Dk + k] : 0.f;
    }
    __syncthreads();

    int ty = tid >> 4, tx = tid & 15;
    int n0 = ty * 8, c0 = tx * 8;

    #pragma unroll
    for (int pass = 0; pass < 2; pass++) {
        const float* Wb = W1s + pass * 64 * 128;
        float acc[8][8];
        #pragma unroll
        for (int a = 0; a < 8; a++)
            #pragma unroll
            for (int b = 0; b < 8; b++) acc[a][b] = 0.f;

        #pragma unroll 4
        for (int k = 0; k < 64; k++) {
            float4 a0 = *(const float4*)&Ns[k * UVP + n0];
            float4 a1 = *(const float4*)&Ns[k * UVP + n0 + 4];
            float4 w0 = *(const float4*)&Wb[k * 128 + c0];
            float4 w1 = *(const float4*)&Wb[k * 128 + c0 + 4];
            float af[8] = {a0.x, a0.y, a0.z, a0.w, a1.x, a1.y, a1.z, a1.w};
            float wf[8] = {w0.x, w0.y, w0.z, w0.w, w1.x, w1.y, w1.z, w1.w};
            #pragma unroll
            for (int a = 0; a < 8; a++)
                #pragma unroll
                for (int b = 0; b < 8; b++) acc[a][b] += af[a] * wf[b];
        }

        float* Out = pass ? g_V : g_U;
        #pragma unroll
        for (int a = 0; a < 8; a++) {
            int gn = n_base + n0 + a;
            if (gn < N) {
                *(float4*)&Out[(size_t)gn * Hk + c0] =
                    make_float4(acc[a][0], acc[a][1], acc[a][2], acc[a][3]);
                *(float4*)&Out[(size_t)gn * Hk + c0 + 4] =
                    make_float4(acc[a][4], acc[a][5], acc[a][6], acc[a][7]);
            }
        }
    }
}

// ---------------- Kernel B: persistent edge kernel, mma.sync tf32 ----------
// Per 128-edge tile, per direction:
//   Hs[e][k'] = tf32(relu(U[s]+V[o]+b1))   (k' = permuted hidden dim)
//   C = Hs @ W2  via m16n8k8 tf32 mma (warp tiling m32 x n32)
//   out[s] += C + b2 via red.global.add.v2
__global__ __launch_bounds__(256, 2) void edge_kernel(const int* __restrict__ edges,
                                                      const float* __restrict__ W2,
                                                      const float* __restrict__ b1,
                                                      const float* __restrict__ b2,
                                                      float* __restrict__ out,
                                                      int E, int tiles) {
    float* smem = (float*)smem_raw;
    float* HS  = smem + F_HS;
    float* W2S = smem + F_W2;
    float* b1s = smem + F_B1;
    float* b2s = smem + F_B2;
    int*   eis = (int*)(smem + F_EIS);
    int*   ejs = (int*)(smem + F_EJS);

    int tid = threadIdx.x, wid = tid >> 5, lane = tid & 31;
    int rr = lane >> 2, q = lane & 3;

    // ---- one-time staging ----
    // W2S[n][k'] = tf32(W2[unit(k')][n]), pitch W2P
    for (int idx = tid; idx < Hk * Dk; idx += 256) {
        int k = idx >> 6, n = idx & 63;
        int unit = (k & ~7) + c_perm[k & 7];
        W2S[n * W2P + k] = to_tf32(W2[unit * Dk + n]);
    }
    if (tid < Hk) b1s[tid] = b1[(tid & ~7) + c_perm[tid & 7]];
    if (tid < Dk) b2s[tid] = b2[tid];
    __syncthreads();

    // warp tiling: 4 m-groups (32 edges) x 2 n-halves (32 cols)
    int e0 = (wid & 3) * 32;
    int n0 = (wid >> 2) * 32;

    for (int t = blockIdx.x; t < tiles; t += gridDim.x) {
        int ebase = t * TE;
        if (tid < TE) {
            int e = ebase + tid;
            int a = 0, b = 0;
            if (e < E) { a = edges[2 * e]; b = edges[2 * e + 1]; }
            eis[tid] = a; ejs[tid] = b;
        }
        __syncthreads();

        #pragma unroll
        for (int dir = 0; dir < 2; dir++) {
            const int* sn = dir ? ejs : eis;    // U-index + scatter target
            const int* on = dir ? eis : ejs;    // V-index

            // ---- gather layer-1 into HS (columns already permuted in g_U/g_V) ----
            #pragma unroll
            for (int it = 0; it < 16; it++) {
                int idx = tid + it * 256;
                int e = idx >> 5;
                int c = (idx & 31) << 2;
                int na = sn[e], nb = on[e];
                float4 u = *(const float4*)&g_U[(size_t)na * Hk + c];
                float4 v = *(const float4*)&g_V[(size_t)nb * Hk + c];
                float4 bb = *(const float4*)&b1s[c];
                float4 h;
                h.x = to_tf32(fmaxf(u.x + v.x + bb.x, 0.f));
                h.y = to_tf32(fmaxf(u.y + v.y + bb.y, 0.f));
                h.z = to_tf32(fmaxf(u.z + v.z + bb.z, 0.f));
                h.w = to_tf32(fmaxf(u.w + v.w + bb.w, 0.f));
                *(float4*)&HS[e * HSP + c] = h;
            }
            __syncthreads();

            // ---- layer-2: mma.sync tf32, K=128 in 16 k8 steps ----
            float acc[2][4][4];
            #pragma unroll
            for (int mt = 0; mt < 2; mt++)
                #pragma unroll
                for (int j = 0; j < 4; j++)
                    #pragma unroll
                    for (int x = 0; x < 4; x++) acc[mt][j][x] = 0.f;

            #pragma unroll 4
            for (int g = 0; g < 16; g++) {
                int col = g * 8 + 2 * q;
                uint32_t a[2][4];
                #pragma unroll
                for (int mt = 0; mt < 2; mt++) {
                    float2 xlo = *(const float2*)&HS[(e0 + 16 * mt + rr) * HSP + col];
                    float2 xhi = *(const float2*)&HS[(e0 + 16 * mt + rr + 8) * HSP + col];
                    a[mt][0] = __float_as_uint(xlo.x);
                    a[mt][1] = __float_as_uint(xhi.x);
                    a[mt][2] = __float_as_uint(xlo.y);
                    a[mt][3] = __float_as_uint(xhi.y);
                }
                #pragma unroll
                for (int j = 0; j < 4; j++) {
                    float2 bf = *(const float2*)&W2S[(n0 + 8 * j + rr) * W2P + col];
                    uint32_t b0 = __float_as_uint(bf.x);
                    uint32_t b1r = __float_as_uint(bf.y);
                    #pragma unroll
                    for (int mt = 0; mt < 2; mt++)
                        mma_tf32(acc[mt][j], a[mt][0], a[mt][1], a[mt][2], a[mt][3], b0, b1r);
                }
            }

            // ---- scatter: C fragments -> red.global.add.v2 ----
            #pragma unroll
            for (int mt = 0; mt < 2; mt++) {
                int er0 = e0 + 16 * mt + rr;       // rows er0, er0+8
                #pragma unroll
                for (int half = 0; half < 2; half++) {
                    int er = er0 + 8 * half;
                    if (ebase + er < E) {
                        int node = sn[er];
                        float* base = out + (size_t)node * Dk;
                        #pragma unroll
                        for (int j = 0; j < 4; j++) {
                            int nb = n0 + 8 * j + 2 * q;
                            float cx = acc[mt][j][2 * half + 0] + b2s[nb];
                            float cy = acc[mt][j][2 * half + 1] + b2s[nb + 1];
                            red_add_v2(base + nb, cx, cy);
                        }
                    }
                }
            }
            __syncthreads();   // HS free for next dir
        }
    }
}

extern "C" void kernel_launch(void* const* d_in, const int* in_sizes, int n_in,
                              void* d_out, int out_size) {
    const float* nodes = (const float*)d_in[0];
    const int*   edges = (const int*)d_in[1];
    const float* W1    = (const float*)d_in[2];
    const float* b1    = (const float*)d_in[3];
    const float* W2    = (const float*)d_in[4];
    const float* b2    = (const float*)d_in[5];
    float* out = (float*)d_out;

    int N = in_sizes[0] / Dk;
    int E = in_sizes[1] / 2;

    static int nsm = 0;
    const int uv_smem = (64 * UVP + 128 * 128) * 4;
    if (!nsm) {
        cudaDeviceGetAttribute(&nsm, cudaDevAttrMultiProcessorCount, 0);
        cudaFuncSetAttribute(uv_kernel,   cudaFuncAttributeMaxDynamicSharedMemorySize, uv_smem);
        cudaFuncSetAttribute(edge_kernel, cudaFuncAttributeMaxDynamicSharedMemorySize, EDGE_SMEM_BYTES);
    }

    int n4 = (N * Dk) / 4;
    copy_kernel<<<(n4 + 255) / 256, 256>>>(nodes, out, n4);

    int uv_blocks = (N + 127) / 128;
    uv_kernel<<<uv_blocks, 256, uv_smem>>>(nodes, W1, N);

    int tiles = (E + TE - 1) / TE;
    edge_kernel<<<2 * nsm, 256, EDGE_SMEM_BYTES>>>(edges, W2, b1, b2, out, E, tiles);
}

// round 6
// speedup vs baseline: 2.1124x; 1.2795x over previous
#include <cuda_runtime.h>
#include <cstdint>

// Shapes: N=100000, D=64, H=128, E=1600000
#define Dk     64
#define Hk     128
#define TE     64       // edges per tile
#define UVP    136      // Us/Vs pitch (floats)
#define W2P    136      // W2s pitch (floats)
#define UVPc   132
#define MAXN   100000

// Scratch: U = nodes @ W1[:64,:] (columns permuted), V = nodes @ W1[64:,:]
__device__ float g_U[(size_t)MAXN * Hk];
__device__ float g_V[(size_t)MAXN * Hk];

// hidden-dim permutation within each 8-group: position s holds unit perm[s]
__device__ __constant__ int c_perm[8] = {0, 4, 1, 5, 2, 6, 3, 7};

// ---------------- smem float-index layout for edge kernel ----------------
#define F_US   0                          // [64][UVP]
#define F_VS   (F_US + TE * UVP)          // [64][UVP]
#define F_W2   (F_VS + TE * UVP)          // [64][W2P]
#define F_B1   (F_W2 + Dk * W2P)          // 128 (permuted)
#define F_B2   (F_B1 + Hk)                // 64
#define F_EIS  (F_B2 + Dk)                // 64 ints
#define F_EJS  (F_EIS + TE)
#define F_TOT  (F_EJS + TE)
#define EDGE_SMEM_BYTES (F_TOT * 4)

extern __shared__ char smem_raw[];

__device__ __forceinline__ uint32_t smem_u32(const void* p) {
    uint32_t a;
    asm("{ .reg .u64 t; cvta.to.shared.u64 t, %1; cvt.u32.u64 %0, t; }" : "=r"(a) : "l"(p));
    return a;
}
__device__ __forceinline__ float to_tf32(float x) {
    float y; asm("cvt.rna.tf32.f32 %0, %1;" : "=f"(y) : "f"(x)); return y;
}
__device__ __forceinline__ void red_add_v2(float* addr, float x, float y) {
    asm volatile("red.global.add.v2.f32 [%0], {%1,%2};"
                 :: "l"(addr), "f"(x), "f"(y) : "memory");
}
__device__ __forceinline__ void cp_async16(void* sdst, const void* gsrc) {
    uint32_t s = smem_u32(sdst);
    asm volatile("cp.async.cg.shared.global [%0], [%1], 16;" :: "r"(s), "l"(gsrc) : "memory");
}
__device__ __forceinline__ void mma_tf32(float c[4],
                                         uint32_t a0, uint32_t a1, uint32_t a2, uint32_t a3,
                                         uint32_t b0, uint32_t b1) {
    asm volatile(
        "mma.sync.aligned.m16n8k8.row.col.f32.tf32.tf32.f32 "
        "{%0,%1,%2,%3}, {%4,%5,%6,%7}, {%8,%9}, {%0,%1,%2,%3};"
        : "+f"(c[0]), "+f"(c[1]), "+f"(c[2]), "+f"(c[3])
        : "r"(a0), "r"(a1), "r"(a2), "r"(a3), "r"(b0), "r"(b1));
}

// ---------------- Kernel 0: out = nodes ----------------
__global__ __launch_bounds__(256) void copy_kernel(const float* __restrict__ nodes,
                                                   float* __restrict__ out, int n4) {
    int i = blockIdx.x * blockDim.x + threadIdx.x;
    if (i < n4) ((float4*)out)[i] = ((const float4*)nodes)[i];
}

// ---------------- Kernel A: U/V precompute (fp32 SIMT, permuted columns) ----
__global__ __launch_bounds__(256) void uv_kernel(const float* __restrict__ nodes,
                                                 const float* __restrict__ W1, int N) {
    float* smem = (float*)smem_raw;
    float* Ns  = smem;                // [64][UVPc]
    float* W1s = smem + 64 * UVPc;    // [128][128] (columns permuted)

    int tid = threadIdx.x;
    for (int idx = tid; idx < 128 * 128; idx += 256) {
        int c = idx & 127;
        int src_c = (c & ~7) + c_perm[c & 7];
        W1s[idx] = W1[(idx & ~127) + src_c];
    }

    int n_base = blockIdx.x * 128;
    for (int idx = tid; idx < 128 * 64; idx += 256) {
        int k = idx & 63, n = idx >> 6;
        int gn = n_base + n;
        Ns[k * UVPc + n] = (gn < N) ? nodes[gn * Dk + k] : 0.f;
    }
    __syncthreads();

    int ty = tid >> 4, tx = tid & 15;
    int n0 = ty * 8, c0 = tx * 8;

    #pragma unroll
    for (int pass = 0; pass < 2; pass++) {
        const float* Wb = W1s + pass * 64 * 128;
        float acc[8][8];
        #pragma unroll
        for (int a = 0; a < 8; a++)
            #pragma unroll
            for (int b = 0; b < 8; b++) acc[a][b] = 0.f;

        #pragma unroll 4
        for (int k = 0; k < 64; k++) {
            float4 a0 = *(const float4*)&Ns[k * UVPc + n0];
            float4 a1 = *(const float4*)&Ns[k * UVPc + n0 + 4];
            float4 w0 = *(const float4*)&Wb[k * 128 + c0];
            float4 w1 = *(const float4*)&Wb[k * 128 + c0 + 4];
            float af[8] = {a0.x, a0.y, a0.z, a0.w, a1.x, a1.y, a1.z, a1.w};
            float wf[8] = {w0.x, w0.y, w0.z, w0.w, w1.x, w1.y, w1.z, w1.w};
            #pragma unroll
            for (int a = 0; a < 8; a++)
                #pragma unroll
                for (int b = 0; b < 8; b++) acc[a][b] += af[a] * wf[b];
        }

        float* Out = pass ? g_V : g_U;
        #pragma unroll
        for (int a = 0; a < 8; a++) {
            int gn = n_base + n0 + a;
            if (gn < N) {
                *(float4*)&Out[(size_t)gn * Hk + c0] =
                    make_float4(acc[a][0], acc[a][1], acc[a][2], acc[a][3]);
                *(float4*)&Out[(size_t)gn * Hk + c0 + 4] =
                    make_float4(acc[a][4], acc[a][5], acc[a][6], acc[a][7]);
            }
        }
    }
}

// ---------------- Kernel B: persistent edge kernel ----------
// Per 64-edge tile, per direction:
//   cp.async-stage raw rows Us = U[sn[e]], Vs = V[on[e]]   (no register latency chain)
//   A-fragments computed on the fly: a = tf32(relu(us + vs + b1))
//   C = H @ W2 via m16n8k8 tf32 mma  (warp = m16 x n32)
//   out[sn] += C + b2 via red.global.add.v2
__global__ __launch_bounds__(256, 2) void edge_kernel(const int* __restrict__ edges,
                                                      const float* __restrict__ W2,
                                                      const float* __restrict__ b1,
                                                      const float* __restrict__ b2,
                                                      float* __restrict__ out,
                                                      int E, int tiles) {
    float* smem = (float*)smem_raw;
    float* US  = smem + F_US;
    float* VS  = smem + F_VS;
    float* W2S = smem + F_W2;
    float* b1s = smem + F_B1;
    float* b2s = smem + F_B2;
    int*   eis = (int*)(smem + F_EIS);
    int*   ejs = (int*)(smem + F_EJS);

    int tid = threadIdx.x, wid = tid >> 5, lane = tid & 31;
    int rr = lane >> 2, q = lane & 3;

    // ---- one-time staging ----
    // W2S[n][k'] = tf32(W2[unit(k')][n])
    for (int idx = tid; idx < Hk * Dk; idx += 256) {
        int k = idx >> 6, n = idx & 63;
        int unit = (k & ~7) + c_perm[k & 7];
        W2S[n * W2P + k] = to_tf32(W2[unit * Dk + n]);
    }
    if (tid < Hk) b1s[tid] = b1[(tid & ~7) + c_perm[tid & 7]];
    if (tid < Dk) b2s[tid] = b2[tid];
    __syncthreads();

    // warp tiling: 4 m16-tiles x 2 n-halves
    int mt = wid & 3;
    int er0 = mt * 16;
    int n0 = (wid >> 2) * 32;

    for (int t = blockIdx.x; t < tiles; t += gridDim.x) {
        int ebase = t * TE;
        if (tid < TE) {
            int e = ebase + tid;
            int a = 0, b = 0;
            if (e < E) { a = edges[2 * e]; b = edges[2 * e + 1]; }
            eis[tid] = a; ejs[tid] = b;
        }
        __syncthreads();

        #pragma unroll
        for (int dir = 0; dir < 2; dir++) {
            const int* sn = dir ? ejs : eis;    // U-index + scatter target
            const int* on = dir ? eis : ejs;    // V-index

            // ---- stage raw U/V rows via cp.async (512B per row) ----
            #pragma unroll
            for (int r = wid; r < TE; r += 8) {
                const float* up = g_U + (size_t)sn[r] * Hk;
                const float* vp = g_V + (size_t)on[r] * Hk;
                cp_async16(&US[r * UVP + lane * 4], up + lane * 4);
                cp_async16(&VS[r * UVP + lane * 4], vp + lane * 4);
            }
            asm volatile("cp.async.commit_group;" ::: "memory");
            asm volatile("cp.async.wait_group 0;" ::: "memory");
            __syncthreads();

            // ---- MMA with fused layer-1 in A-fragment loads ----
            float acc[4][4];
            #pragma unroll
            for (int j = 0; j < 4; j++)
                #pragma unroll
                for (int x = 0; x < 4; x++) acc[j][x] = 0.f;

            #pragma unroll 4
            for (int g = 0; g < 16; g++) {
                int col = g * 8 + 2 * q;
                float2 bb = *(const float2*)&b1s[col];
                float2 u0 = *(const float2*)&US[(er0 + rr) * UVP + col];
                float2 v0 = *(const float2*)&VS[(er0 + rr) * UVP + col];
                float2 u1 = *(const float2*)&US[(er0 + rr + 8) * UVP + col];
                float2 v1 = *(const float2*)&VS[(er0 + rr + 8) * UVP + col];
                uint32_t a0 = __float_as_uint(to_tf32(fmaxf(u0.x + v0.x + bb.x, 0.f)));
                uint32_t a2 = __float_as_uint(to_tf32(fmaxf(u0.y + v0.y + bb.y, 0.f)));
                uint32_t a1 = __float_as_uint(to_tf32(fmaxf(u1.x + v1.x + bb.x, 0.f)));
                uint32_t a3 = __float_as_uint(to_tf32(fmaxf(u1.y + v1.y + bb.y, 0.f)));
                #pragma unroll
                for (int j = 0; j < 4; j++) {
                    float2 bf = *(const float2*)&W2S[(n0 + 8 * j + rr) * W2P + col];
                    mma_tf32(acc[j], a0, a1, a2, a3,
                             __float_as_uint(bf.x), __float_as_uint(bf.y));
                }
            }

            // ---- scatter ----
            #pragma unroll
            for (int half = 0; half < 2; half++) {
                int er = er0 + rr + 8 * half;
                if (ebase + er < E) {
                    int node = sn[er];
                    float* base = out + (size_t)node * Dk;
                    #pragma unroll
                    for (int j = 0; j < 4; j++) {
                        int nb = n0 + 8 * j + 2 * q;
                        float cx = acc[j][2 * half + 0] + b2s[nb];
                        float cy = acc[j][2 * half + 1] + b2s[nb + 1];
                        red_add_v2(base + nb, cx, cy);
                    }
                }
            }
            __syncthreads();   // US/VS free for next dir
        }
    }
}

extern "C" void kernel_launch(void* const* d_in, const int* in_sizes, int n_in,
                              void* d_out, int out_size) {
    const float* nodes = (const float*)d_in[0];
    const int*   edges = (const int*)d_in[1];
    const float* W1    = (const float*)d_in[2];
    const float* b1    = (const float*)d_in[3];
    const float* W2    = (const float*)d_in[4];
    const float* b2    = (const float*)d_in[5];
    float* out = (float*)d_out;

    int N = in_sizes[0] / Dk;
    int E = in_sizes[1] / 2;

    static int nsm = 0;
    const int uv_smem = (64 * UVPc + 128 * 128) * 4;
    if (!nsm) {
        cudaDeviceGetAttribute(&nsm, cudaDevAttrMultiProcessorCount, 0);
        cudaFuncSetAttribute(uv_kernel,   cudaFuncAttributeMaxDynamicSharedMemorySize, uv_smem);
        cudaFuncSetAttribute(edge_kernel, cudaFuncAttributeMaxDynamicSharedMemorySize, EDGE_SMEM_BYTES);
    }

    int n4 = (N * Dk) / 4;
    copy_kernel<<<(n4 + 255) / 256, 256>>>(nodes, out, n4);

    int uv_blocks = (N + 127) / 128;
    uv_kernel<<<uv_blocks, 256, uv_smem>>>(nodes, W1, N);

    int tiles = (E + TE - 1) / TE;
    edge_kernel<<<2 * nsm, 256, EDGE_SMEM_BYTES>>>(edges, W2, b1, b2, out, E, tiles);
}